// round 1
// baseline (speedup 1.0000x reference)
#include <cuda_runtime.h>
#include <cstdint>

// Problem constants
constexpr int V  = 32000;
constexpr int H  = 1024;
constexpr int B  = 64;
constexpr int T  = 1024;
constexpr int NC = 16;               // attention T-chunks per batch (T/64)
constexpr int HID_OFF  = B * V;              // 2048000
constexpr int ATTN_OFF = HID_OFF + B * H;    // 2113536

// ---------------- scratch (device globals: no allocation allowed) ------------
__device__ float g_emb[B * H];
__device__ float g_gx[B * 3 * H];
__device__ float g_gh[B * 3 * H];
__device__ float g_cat[B * 2 * H];          // [hnew | context]
__device__ float g_scores[B * T];
__device__ float g_pm[B * NC];
__device__ float g_ps[B * NC];
__device__ float g_pc[B * NC * H];
__device__ float g_cop[B * H];
__device__ float g_co[B * H];

// ---------------- packed f32x2 FMA (FFMA2) ----------------------------------
__device__ __forceinline__ void ffma2(unsigned long long& d,
                                      unsigned long long a,
                                      unsigned long long b) {
    asm("fma.rn.f32x2 %0, %1, %2, %0;" : "+l"(d) : "l"(a), "l"(b));
}

// ---------------- generic tiled GEMM: C[b][n] += A[b][:] . W[n][:] -----------
// Block: 256 threads, tile 64b x 64n, K chunked by 64.
// Thread (tx,ty): n = nb + tx + 16j (j<4, strided), b = 4*ty + i (i<4).
template <int N, int K, bool ATOMIC>
__device__ __forceinline__ void gemm_core(const float* __restrict__ A,
                                          const float* __restrict__ W,
                                          float* __restrict__ C) {
    __shared__ float4 As4[16 * 65];
    __shared__ float4 Ws4[16 * 65];

    const int tid = threadIdx.x;
    const int tx  = tid & 15;
    const int ty  = tid >> 4;
    const int nb  = blockIdx.x * 64;
    const int kLen = K / gridDim.y;
    const int k0   = blockIdx.y * kLen;

    unsigned long long acc[4][4];
#pragma unroll
    for (int i = 0; i < 4; ++i)
#pragma unroll
        for (int j = 0; j < 4; ++j) acc[i][j] = 0ull;

    for (int kc = k0; kc < k0 + kLen; kc += 64) {
#pragma unroll
        for (int r = 0; r < 4; ++r) {
            int s   = tid + r * 256;    // 0..1023
            int row = s >> 4;           // b for A, local n for W
            int kq  = s & 15;
            As4[kq * 65 + row] =
                *reinterpret_cast<const float4*>(&A[(size_t)row * K + kc + kq * 4]);
            Ws4[kq * 65 + row] =
                *reinterpret_cast<const float4*>(&W[(size_t)(nb + row) * K + kc + kq * 4]);
        }
        __syncthreads();

        const ulonglong2* As2 = reinterpret_cast<const ulonglong2*>(As4);
        const ulonglong2* Ws2 = reinterpret_cast<const ulonglong2*>(Ws4);
#pragma unroll 4
        for (int kq = 0; kq < 16; ++kq) {
            ulonglong2 a[4], w[4];
#pragma unroll
            for (int i = 0; i < 4; ++i) a[i] = As2[kq * 65 + ty * 4 + i];
#pragma unroll
            for (int j = 0; j < 4; ++j) w[j] = Ws2[kq * 65 + tx + 16 * j];
#pragma unroll
            for (int i = 0; i < 4; ++i)
#pragma unroll
                for (int j = 0; j < 4; ++j) ffma2(acc[i][j], a[i].x, w[j].x);
#pragma unroll
            for (int i = 0; i < 4; ++i)
#pragma unroll
                for (int j = 0; j < 4; ++j) ffma2(acc[i][j], a[i].y, w[j].y);
        }
        __syncthreads();
    }

#pragma unroll
    for (int i = 0; i < 4; ++i)
#pragma unroll
        for (int j = 0; j < 4; ++j) {
            float lo = __uint_as_float((unsigned)(acc[i][j] & 0xffffffffull));
            float hi = __uint_as_float((unsigned)(acc[i][j] >> 32));
            float sum = lo + hi;
            int bb = ty * 4 + i;
            int nn = nb + tx + 16 * j;
            size_t idx = (size_t)bb * N + nn;
            if (ATOMIC) atomicAdd(&C[idx], sum);
            else        C[idx] += sum;
        }
}

__global__ void __launch_bounds__(256) k_gemm_gx(const float* __restrict__ W) {
    gemm_core<3 * H, H, true>(g_emb, W, g_gx);
}
__global__ void __launch_bounds__(256) k_gemm_gh(const float* __restrict__ A,
                                                 const float* __restrict__ W) {
    gemm_core<3 * H, H, true>(A, W, g_gh);
}
__global__ void __launch_bounds__(256) k_gemm_cat(const float* __restrict__ W) {
    gemm_core<H, 2 * H, true>(g_cat, W, g_cop);
}
__global__ void __launch_bounds__(256) k_gemm_out(const float* __restrict__ W,
                                                  float* __restrict__ C) {
    gemm_core<V, H, false>(g_co, W, C);
}

// ---------------- bias broadcast init ----------------------------------------
__device__ __forceinline__ void init_core(float* C, const float* bias, int N) {
    int idx = blockIdx.x * blockDim.x + threadIdx.x;
    C[idx] = bias[idx % N];
}
__global__ void k_init_gx(const float* b)  { init_core(g_gx, b, 3 * H); }
__global__ void k_init_gh(const float* b)  { init_core(g_gh, b, 3 * H); }
__global__ void k_init_cop(const float* b) { init_core(g_cop, b, H); }
__global__ void k_init_out(float* C, const float* b) { init_core(C, b, V); }

// ---------------- embedding gather -------------------------------------------
__global__ void k_gather(const int* __restrict__ seq, const float* __restrict__ emb) {
    int idx = blockIdx.x * 256 + threadIdx.x;   // 0..65535
    int b = idx >> 10, h = idx & 1023;
    g_emb[idx] = emb[(size_t)seq[b] * H + h];
}

// ---------------- GRU gate fusion --------------------------------------------
__global__ void k_gate(const float* __restrict__ h0, float* __restrict__ hid_out) {
    int idx = blockIdx.x * 256 + threadIdx.x;   // 0..65535
    int b = idx >> 10, c = idx & 1023;
    int base = b * 3072;
    float xr = g_gx[base + c],        hr = g_gh[base + c];
    float xz = g_gx[base + 1024 + c], hz = g_gh[base + 1024 + c];
    float xn = g_gx[base + 2048 + c], hn = g_gh[base + 2048 + c];
    float r = 1.f / (1.f + __expf(-(xr + hr)));
    float z = 1.f / (1.f + __expf(-(xz + hz)));
    float n = tanhf(xn + r * hn);
    float h = (1.f - z) * n + z * h0[idx];
    g_cat[b * 2048 + c] = h;    // hnew half of concat input
    hid_out[idx] = h;           // hidden output
}

// ---------------- one-pass attention (online softmax + context) ---------------
// Block = (batch b, chunk c): 64 timesteps. 256 threads, thread owns 4 h's.
__global__ void __launch_bounds__(256) k_attn(const float* __restrict__ enc) {
    __shared__ __align__(16) float wp[2][8];
    const int b = blockIdx.x;
    const int c = blockIdx.y;
    const int tid  = threadIdx.x;
    const int lane = tid & 31, wid = tid >> 5;
    const int h4 = tid * 4;

    float4 hn = *reinterpret_cast<const float4*>(&g_cat[b * 2048 + h4]);
    float4 cx = make_float4(0.f, 0.f, 0.f, 0.f);
    float m = -1e30f, s = 0.f;
    const int t0 = c * 64;

    for (int it = 0; it < 64; ++it) {
        int t = t0 + it;
        float4 e = *reinterpret_cast<const float4*>(&enc[((size_t)t * B + b) * H + h4]);
        float p = e.x * hn.x + e.y * hn.y + e.z * hn.z + e.w * hn.w;
#pragma unroll
        for (int o = 16; o > 0; o >>= 1) p += __shfl_xor_sync(0xffffffffu, p, o);
        int par = it & 1;
        if (lane == 0) wp[par][wid] = p;
        __syncthreads();
        float4 q0 = *reinterpret_cast<const float4*>(&wp[par][0]);
        float4 q1 = *reinterpret_cast<const float4*>(&wp[par][4]);
        float st = ((q0.x + q0.y) + (q0.z + q0.w)) + ((q1.x + q1.y) + (q1.z + q1.w));
        if (tid == 0) g_scores[b * T + t] = st;
        if (st > m) {
            float al = __expf(m - st);
            cx.x *= al; cx.y *= al; cx.z *= al; cx.w *= al;
            s *= al;
            m = st;
        }
        float w = __expf(st - m);
        s += w;
        cx.x += w * e.x; cx.y += w * e.y; cx.z += w * e.z; cx.w += w * e.w;
    }

    *reinterpret_cast<float4*>(&g_pc[((size_t)b * NC + c) * H + h4]) = cx;
    if (tid == 0) { g_pm[b * NC + c] = m; g_ps[b * NC + c] = s; }
}

// ---------------- attention combine: context + attn weights -------------------
__global__ void __launch_bounds__(256) k_combine(float* __restrict__ attn_out) {
    const int b = blockIdx.x;
    const int tid = threadIdx.x;
    float pm[NC], ps[NC];
#pragma unroll
    for (int i = 0; i < NC; ++i) { pm[i] = g_pm[b * NC + i]; ps[i] = g_ps[b * NC + i]; }
    float M = pm[0];
#pragma unroll
    for (int i = 1; i < NC; ++i) M = fmaxf(M, pm[i]);
    float S = 0.f, wts[NC];
#pragma unroll
    for (int i = 0; i < NC; ++i) { wts[i] = __expf(pm[i] - M); S += ps[i] * wts[i]; }
    float invS = 1.0f / S;

    int h4 = tid * 4;
    float4 cxa = make_float4(0.f, 0.f, 0.f, 0.f);
#pragma unroll
    for (int i = 0; i < NC; ++i) {
        float4 pcv = *reinterpret_cast<const float4*>(&g_pc[((size_t)b * NC + i) * H + h4]);
        float w = wts[i];
        cxa.x += w * pcv.x; cxa.y += w * pcv.y; cxa.z += w * pcv.z; cxa.w += w * pcv.w;
    }
    cxa.x *= invS; cxa.y *= invS; cxa.z *= invS; cxa.w *= invS;
    *reinterpret_cast<float4*>(&g_cat[b * 2048 + 1024 + h4]) = cxa;   // context half

#pragma unroll
    for (int j = 0; j < 4; ++j) {
        int t = tid + j * 256;
        attn_out[b * T + t] = __expf(g_scores[b * T + t] - M) * invS;
    }
}

// ---------------- tanh epilogue of concat GEMM --------------------------------
__global__ void k_tanh() {
    int idx = blockIdx.x * 256 + threadIdx.x;
    g_co[idx] = tanhf(g_cop[idx]);
}

// ---------------- launch ------------------------------------------------------
extern "C" void kernel_launch(void* const* d_in, const int* in_sizes, int n_in,
                              void* d_out, int out_size) {
    (void)in_sizes; (void)n_in; (void)out_size;
    const int*   seq  = (const int*)d_in[0];
    const float* h0   = (const float*)d_in[1];
    const float* enc  = (const float*)d_in[2];
    const float* emb  = (const float*)d_in[3];
    const float* w_ih = (const float*)d_in[4];
    const float* w_hh = (const float*)d_in[5];
    const float* b_ih = (const float*)d_in[6];
    const float* b_hh = (const float*)d_in[7];
    const float* cW   = (const float*)d_in[8];
    const float* cb   = (const float*)d_in[9];
    const float* oW   = (const float*)d_in[10];
    const float* ob   = (const float*)d_in[11];
    float* out = (float*)d_out;

    k_gather<<<256, 256>>>(seq, emb);
    k_init_gx<<<768, 256>>>(b_ih);
    k_init_gh<<<768, 256>>>(b_hh);
    k_init_cop<<<256, 256>>>(cb);
    k_init_out<<<8000, 256>>>(out, ob);

    k_gemm_gx<<<dim3(48, 4), 256>>>(w_ih);
    k_gemm_gh<<<dim3(48, 4), 256>>>(h0, w_hh);
    k_gate<<<256, 256>>>(h0, out + HID_OFF);

    k_attn<<<dim3(B, NC), 256>>>(enc);
    k_combine<<<B, 256>>>(out + ATTN_OFF);

    k_gemm_cat<<<dim3(16, 8), 256>>>(cW);
    k_tanh<<<256, 256>>>();
    k_gemm_out<<<dim3(V / 64, 1), 256>>>(oW, out);
}